// round 2
// baseline (speedup 1.0000x reference)
#include <cuda_runtime.h>
#include <math.h>

#define Bb 32
#define Tt 1024
#define Dd 256
#define BT (Bb*Tt)
#define MAXE 64
#define LN_EPS 1e-5f
#define EPS_ADJ 1e-6f

typedef unsigned long long u64;

__device__ __forceinline__ u64 fma2(u64 a, u64 b, u64 c) {
    u64 d;
    asm("fma.rn.f32x2 %0,%1,%2,%3;" : "=l"(d) : "l"(a), "l"(b), "l"(c));
    return d;
}
__device__ __forceinline__ float2 unpack2(u64 v) {
    float2 p;
    asm("mov.b64 {%0,%1},%2;" : "=f"(p.x), "=f"(p.y) : "l"(v));
    return p;
}

// ---------------- device scratch (static, allocation-free) ----------------
__device__ float    g_xn[BT*Dd];        // normalized x
__device__ float    g_s0[BT*Dd];        // scratch ping
__device__ float    g_s1[BT*Dd];        // scratch pong
__device__ float    g_mf[BT];           // mask as float
__device__ int      g_top2[BT*2];       // top-2 indices per row
__device__ unsigned g_bits[BT*(Tt/32)]; // adjacency bitmap
__device__ float    g_rinv[BT];         // 1/sqrt(rowsum+eps)
__device__ int      g_ecols[BT*MAXE];
__device__ float    g_evals[BT*MAXE];
__device__ int      g_ecnt[BT];

// ---------------- row normalize + mask cast ----------------
__global__ void k_normalize(const float* __restrict__ x, const int* __restrict__ mask) {
    int row = blockIdx.x;
    int d = threadIdx.x;
    float v = x[row*Dd + d];
    __shared__ float red[8];
    float ss = v*v;
    #pragma unroll
    for (int o = 16; o; o >>= 1) ss += __shfl_xor_sync(~0u, ss, o);
    if ((threadIdx.x & 31) == 0) red[threadIdx.x >> 5] = ss;
    __syncthreads();
    if (threadIdx.x < 8) {
        float t = red[threadIdx.x];
        #pragma unroll
        for (int o = 4; o; o >>= 1) t += __shfl_xor_sync(0xff, t, o);
        if (threadIdx.x == 0) red[0] = t;
    }
    __syncthreads();
    float nrm = sqrtf(red[0]);
    float rn = 1.f / fmaxf(nrm, 1e-12f);
    g_xn[row*Dd + d] = v * rn;
    if (d == 0) g_mf[row] = (float)mask[row];
}

// ================= packed-f32x2 sim GEMM + streamed top-2 =================
#define TIr 128
#define TJc 128
#define KT  16

__device__ __forceinline__ bool tgt(float v, int j, float v2, int j2) {
    return (v > v2) || (v == v2 && j < j2);
}

__global__ __launch_bounds__(256, 2) void k_simtop2() {
    __shared__ float2 As2[KT][TIr+2];   // duplicated (a,a), pitch 130 float2 (1040B, 16B-mult)
    __shared__ float  Bs [KT][TJc+4];   // pitch 132 floats (528B, 16B-mult)
    __shared__ float  rmask[TIr];
    __shared__ float  smask[TJc];

    int b  = blockIdx.y;
    int i0 = blockIdx.x * TIr;
    int rb = b * Tt;
    int tid = threadIdx.x;
    int tx = tid & 15, ty = tid >> 4;
    int lr = tid >> 1;          // loader row 0..127
    int lk = (tid & 1) * 8;     // loader k offset 0 or 8

    if (tid < TIr) rmask[tid] = g_mf[rb + i0 + tid];

    float v1[8], v2[8]; int j1[8], j2[8];
    #pragma unroll
    for (int r = 0; r < 8; r++) { v1[r] = -1e30f; v2[r] = -1e30f; j1[r] = 0; j2[r] = 0; }

    for (int j0 = 0; j0 < Tt; j0 += TJc) {
        __syncthreads();
        if (tid < TJc) smask[tid] = g_mf[rb + j0 + tid];

        u64 acc[8][4];
        #pragma unroll
        for (int r = 0; r < 8; r++)
            #pragma unroll
            for (int c = 0; c < 4; c++) acc[r][c] = 0ull;

        for (int k0 = 0; k0 < Dd; k0 += KT) {
            __syncthreads();
            {
                const float4 a0 = *(const float4*)&g_xn[(rb+i0+lr)*Dd + k0 + lk];
                const float4 a1 = *(const float4*)&g_xn[(rb+i0+lr)*Dd + k0 + lk + 4];
                As2[lk+0][lr] = make_float2(a0.x, a0.x);
                As2[lk+1][lr] = make_float2(a0.y, a0.y);
                As2[lk+2][lr] = make_float2(a0.z, a0.z);
                As2[lk+3][lr] = make_float2(a0.w, a0.w);
                As2[lk+4][lr] = make_float2(a1.x, a1.x);
                As2[lk+5][lr] = make_float2(a1.y, a1.y);
                As2[lk+6][lr] = make_float2(a1.z, a1.z);
                As2[lk+7][lr] = make_float2(a1.w, a1.w);
                const float4 b0 = *(const float4*)&g_xn[(rb+j0+lr)*Dd + k0 + lk];
                const float4 b1 = *(const float4*)&g_xn[(rb+j0+lr)*Dd + k0 + lk + 4];
                Bs[lk+0][lr] = b0.x; Bs[lk+1][lr] = b0.y;
                Bs[lk+2][lr] = b0.z; Bs[lk+3][lr] = b0.w;
                Bs[lk+4][lr] = b1.x; Bs[lk+5][lr] = b1.y;
                Bs[lk+6][lr] = b1.z; Bs[lk+7][lr] = b1.w;
            }
            __syncthreads();
            #pragma unroll
            for (int k = 0; k < KT; k++) {
                ulonglong2 A01 = *(ulonglong2*)&As2[k][ty*8 + 0];
                ulonglong2 A23 = *(ulonglong2*)&As2[k][ty*8 + 2];
                ulonglong2 A45 = *(ulonglong2*)&As2[k][ty*8 + 4];
                ulonglong2 A67 = *(ulonglong2*)&As2[k][ty*8 + 6];
                ulonglong2 B03 = *(ulonglong2*)&Bs[k][tx*8 + 0];
                ulonglong2 B47 = *(ulonglong2*)&Bs[k][tx*8 + 4];
                u64 ap[8] = {A01.x, A01.y, A23.x, A23.y, A45.x, A45.y, A67.x, A67.y};
                u64 bp[4] = {B03.x, B03.y, B47.x, B47.y};
                #pragma unroll
                for (int r = 0; r < 8; r++)
                    #pragma unroll
                    for (int c = 0; c < 4; c++)
                        acc[r][c] = fma2(ap[r], bp[c], acc[r][c]);
            }
        }
        // epilogue: masked sim, diag=-1, streamed top-2
        #pragma unroll
        for (int r = 0; r < 8; r++) {
            int gi = i0 + ty*8 + r;
            float mi = rmask[ty*8 + r];
            #pragma unroll
            for (int c = 0; c < 4; c++) {
                float2 p = unpack2(acc[r][c]);
                int gj0 = j0 + tx*8 + c*2;
                float s0 = p.x * mi * smask[tx*8 + c*2 + 0];
                float s1 = p.y * mi * smask[tx*8 + c*2 + 1];
                if (gj0 == gi)     s0 = -1.0f;
                if (gj0 + 1 == gi) s1 = -1.0f;
                if (s0 > v1[r])      { v2[r]=v1[r]; j2[r]=j1[r]; v1[r]=s0; j1[r]=gj0; }
                else if (s0 > v2[r]) { v2[r]=s0; j2[r]=gj0; }
                if (s1 > v1[r])      { v2[r]=v1[r]; j2[r]=j1[r]; v1[r]=s1; j1[r]=gj0+1; }
                else if (s1 > v2[r]) { v2[r]=s1; j2[r]=gj0+1; }
            }
        }
    }
    // merge across the 16 tx-lanes (lanes sharing ty live in one 16-lane segment)
    #pragma unroll
    for (int r = 0; r < 8; r++) {
        #pragma unroll
        for (int off = 8; off; off >>= 1) {
            float ov1 = __shfl_down_sync(~0u, v1[r], off, 16);
            int   oj1 = __shfl_down_sync(~0u, j1[r], off, 16);
            float ov2 = __shfl_down_sync(~0u, v2[r], off, 16);
            int   oj2 = __shfl_down_sync(~0u, j2[r], off, 16);
            if (tgt(ov1, oj1, v1[r], j1[r])) { v2[r]=v1[r]; j2[r]=j1[r]; v1[r]=ov1; j1[r]=oj1; }
            else if (tgt(ov1, oj1, v2[r], j2[r])) { v2[r]=ov1; j2[r]=oj1; }
            if (tgt(ov2, oj2, v1[r], j1[r])) { v2[r]=v1[r]; j2[r]=j1[r]; v1[r]=ov2; j1[r]=oj2; }
            else if (tgt(ov2, oj2, v2[r], j2[r])) { v2[r]=ov2; j2[r]=oj2; }
        }
        if (tx == 0) {
            int grow = rb + i0 + ty*8 + r;
            g_top2[grow*2 + 0] = j1[r];
            g_top2[grow*2 + 1] = j2[r];
        }
    }
}

// ---------------- adjacency bitmap ----------------
__global__ void k_clear() {
    int i = blockIdx.x*256 + threadIdx.x;
    if (i < BT*(Tt/32)) g_bits[i] = 0u;
}

__global__ void k_setbits() {
    int row = blockIdx.x*256 + threadIdx.x;
    if (row >= BT) return;
    int b = row / Tt, i = row % Tt;
    unsigned* wb = &g_bits[row*(Tt/32)];
    atomicOr(&wb[i >> 5], 1u << (i & 31));
    if (i > 0)      atomicOr(&wb[(i-1) >> 5], 1u << ((i-1) & 31));
    if (i < Tt-1)   atomicOr(&wb[(i+1) >> 5], 1u << ((i+1) & 31));
    float mi = g_mf[row];
    #pragma unroll
    for (int t = 0; t < 2; t++) {
        int j = g_top2[row*2 + t];
        float mj = g_mf[b*Tt + j];
        if (mi*mj != 0.f) {
            atomicOr(&wb[j >> 5], 1u << (j & 31));
            atomicOr(&g_bits[(b*Tt + j)*(Tt/32) + (i >> 5)], 1u << (i & 31));
        }
    }
}

// ---------------- edge extraction (warp per row) ----------------
__global__ __launch_bounds__(256) void k_edges() {
    int warp = (blockIdx.x*256 + threadIdx.x) >> 5;
    int lane = threadIdx.x & 31;
    if (warp >= BT) return;
    int row = warp;
    int b = row / Tt, i = row % Tt;
    float a[8];
    #pragma unroll
    for (int u = 0; u < 8; u++) a[u] = g_xn[row*Dd + lane + 32*u];
    float mi = g_mf[row];
    float rowsum = 0.f;
    int cnt = 0;
    for (int w = 0; w < Tt/32; w++) {
        unsigned bitsw = g_bits[row*(Tt/32) + w];
        while (bitsw) {
            int bit = __ffs(bitsw) - 1;
            bitsw &= bitsw - 1;
            int j = w*32 + bit;
            int jr = b*Tt + j;
            float dot = 0.f;
            #pragma unroll
            for (int u = 0; u < 8; u++) dot = fmaf(a[u], g_xn[jr*Dd + lane + 32*u], dot);
            #pragma unroll
            for (int o = 16; o; o >>= 1) dot += __shfl_xor_sync(~0u, dot, o);
            float val = dot * mi * g_mf[jr];
            if (j == i) val += 1.0f;
            rowsum += val;
            if (lane == 0 && cnt < MAXE) {
                g_ecols[row*MAXE + cnt] = j;
                g_evals[row*MAXE + cnt] = val;
            }
            cnt++;
        }
    }
    if (lane == 0) {
        g_ecnt[row] = min(cnt, MAXE);
        g_rinv[row] = rsqrtf(rowsum + EPS_ADJ);
    }
}

// ---------------- sparse adj @ h ----------------
__global__ __launch_bounds__(256) void k_spmm(const float* __restrict__ hin,
                                              float* __restrict__ hout) {
    int row = blockIdx.x;
    int d = threadIdx.x;
    int b = row / Tt;
    int cnt = g_ecnt[row];
    float ri = g_rinv[row], mi = g_mf[row];
    float acc = 0.f;
    for (int e = 0; e < cnt; e++) {
        int j = g_ecols[row*MAXE + e];
        int jr = b*Tt + j;
        float w = g_evals[row*MAXE + e] * ri * g_rinv[jr] * mi * g_mf[jr];
        acc = fmaf(w, hin[jr*Dd + d], acc);
    }
    hout[row*Dd + d] = acc;
}

// ======== packed-f32x2 dense h @ W^T + bias + ELU ========
__global__ __launch_bounds__(256, 2) void k_gemm_bias_elu(const float* __restrict__ A,
                                                          const float* __restrict__ W,
                                                          const float* __restrict__ bias,
                                                          float* __restrict__ out) {
    __shared__ float2 As2[KT][TIr+2];
    __shared__ float  Bs [KT][TJc+4];
    int r0 = blockIdx.x * TIr;
    int o0 = blockIdx.y * TJc;
    int tid = threadIdx.x;
    int tx = tid & 15, ty = tid >> 4;
    int lr = tid >> 1;
    int lk = (tid & 1) * 8;

    u64 acc[8][4];
    #pragma unroll
    for (int r = 0; r < 8; r++)
        #pragma unroll
        for (int c = 0; c < 4; c++) acc[r][c] = 0ull;

    for (int k0 = 0; k0 < Dd; k0 += KT) {
        __syncthreads();
        {
            const float4 a0 = *(const float4*)&A[(r0+lr)*Dd + k0 + lk];
            const float4 a1 = *(const float4*)&A[(r0+lr)*Dd + k0 + lk + 4];
            As2[lk+0][lr] = make_float2(a0.x, a0.x);
            As2[lk+1][lr] = make_float2(a0.y, a0.y);
            As2[lk+2][lr] = make_float2(a0.z, a0.z);
            As2[lk+3][lr] = make_float2(a0.w, a0.w);
            As2[lk+4][lr] = make_float2(a1.x, a1.x);
            As2[lk+5][lr] = make_float2(a1.y, a1.y);
            As2[lk+6][lr] = make_float2(a1.z, a1.z);
            As2[lk+7][lr] = make_float2(a1.w, a1.w);
            const float4 b0 = *(const float4*)&W[(o0+lr)*Dd + k0 + lk];
            const float4 b1 = *(const float4*)&W[(o0+lr)*Dd + k0 + lk + 4];
            Bs[lk+0][lr] = b0.x; Bs[lk+1][lr] = b0.y;
            Bs[lk+2][lr] = b0.z; Bs[lk+3][lr] = b0.w;
            Bs[lk+4][lr] = b1.x; Bs[lk+5][lr] = b1.y;
            Bs[lk+6][lr] = b1.z; Bs[lk+7][lr] = b1.w;
        }
        __syncthreads();
        #pragma unroll
        for (int k = 0; k < KT; k++) {
            ulonglong2 A01 = *(ulonglong2*)&As2[k][ty*8 + 0];
            ulonglong2 A23 = *(ulonglong2*)&As2[k][ty*8 + 2];
            ulonglong2 A45 = *(ulonglong2*)&As2[k][ty*8 + 4];
            ulonglong2 A67 = *(ulonglong2*)&As2[k][ty*8 + 6];
            ulonglong2 B03 = *(ulonglong2*)&Bs[k][tx*8 + 0];
            ulonglong2 B47 = *(ulonglong2*)&Bs[k][tx*8 + 4];
            u64 ap[8] = {A01.x, A01.y, A23.x, A23.y, A45.x, A45.y, A67.x, A67.y};
            u64 bp[4] = {B03.x, B03.y, B47.x, B47.y};
            #pragma unroll
            for (int r = 0; r < 8; r++)
                #pragma unroll
                for (int c = 0; c < 4; c++)
                    acc[r][c] = fma2(ap[r], bp[c], acc[r][c]);
        }
    }
    #pragma unroll
    for (int r = 0; r < 8; r++) {
        int grow = r0 + ty*8 + r;
        #pragma unroll
        for (int c = 0; c < 4; c++) {
            float2 p = unpack2(acc[r][c]);
            int o = o0 + tx*8 + c*2;
            float va = p.x + bias[o];
            float vb = p.y + bias[o+1];
            va = (va > 0.f) ? va : expm1f(va);
            vb = (vb > 0.f) ? vb : expm1f(vb);
            out[grow*Dd + o]     = va;
            out[grow*Dd + o + 1] = vb;
        }
    }
}

// ---------------- LayerNorm over D ----------------
__global__ void k_ln(const float* __restrict__ in, const float* __restrict__ g,
                     const float* __restrict__ be, float* __restrict__ out) {
    int row = blockIdx.x;
    int d = threadIdx.x;
    float v = in[row*Dd + d];
    __shared__ float red[8];

    float s = v;
    #pragma unroll
    for (int o = 16; o; o >>= 1) s += __shfl_xor_sync(~0u, s, o);
    if ((threadIdx.x & 31) == 0) red[threadIdx.x >> 5] = s;
    __syncthreads();
    if (threadIdx.x < 8) {
        float t = red[threadIdx.x];
        #pragma unroll
        for (int o = 4; o; o >>= 1) t += __shfl_xor_sync(0xff, t, o);
        if (threadIdx.x == 0) red[0] = t;
    }
    __syncthreads();
    float mu = red[0] * (1.f/Dd);
    __syncthreads();

    float dv = v - mu;
    float s2 = dv*dv;
    #pragma unroll
    for (int o = 16; o; o >>= 1) s2 += __shfl_xor_sync(~0u, s2, o);
    if ((threadIdx.x & 31) == 0) red[threadIdx.x >> 5] = s2;
    __syncthreads();
    if (threadIdx.x < 8) {
        float t = red[threadIdx.x];
        #pragma unroll
        for (int o = 4; o; o >>= 1) t += __shfl_xor_sync(0xff, t, o);
        if (threadIdx.x == 0) red[0] = t;
    }
    __syncthreads();
    float var = red[0] * (1.f/Dd);
    out[row*Dd + d] = dv * rsqrtf(var + LN_EPS) * g[d] + be[d];
}

// ---------------- launch ----------------
extern "C" void kernel_launch(void* const* d_in, const int* in_sizes, int n_in,
                              void* d_out, int out_size) {
    const float* x    = (const float*)d_in[0];
    const int*   mask = (const int*)  d_in[1];
    const float* W0 = (const float*)d_in[2];
    const float* b0 = (const float*)d_in[3];
    const float* g0 = (const float*)d_in[4];
    const float* be0= (const float*)d_in[5];
    const float* W1 = (const float*)d_in[6];
    const float* b1 = (const float*)d_in[7];
    const float* g1 = (const float*)d_in[8];
    const float* be1= (const float*)d_in[9];
    float* out = (float*)d_out;

    float *s0, *s1;
    cudaGetSymbolAddress((void**)&s0, g_s0);
    cudaGetSymbolAddress((void**)&s1, g_s1);

    k_normalize<<<BT, 256>>>(x, mask);
    k_clear<<<(BT*(Tt/32) + 255)/256, 256>>>();
    k_simtop2<<<dim3(Tt/TIr, Bb), 256>>>();
    k_setbits<<<BT/256, 256>>>();
    k_edges<<<(BT*32)/256, 256>>>();

    // layer 1
    k_spmm<<<BT, 256>>>(x, s0);
    k_gemm_bias_elu<<<dim3(BT/TIr, Dd/TJc), 256>>>(s0, W0, b0, s1);
    k_ln<<<BT, 256>>>(s1, g0, be0, s0);
    // layer 2
    k_spmm<<<BT, 256>>>(s0, s1);
    k_gemm_bias_elu<<<dim3(BT/TIr, Dd/TJc), 256>>>(s1, W1, b1, s0);
    k_ln<<<BT, 256>>>(s0, g1, be1, out);
}

// round 3
// speedup vs baseline: 1.3998x; 1.3998x over previous
#include <cuda_runtime.h>
#include <math.h>

#define Bb 32
#define Tt 1024
#define Dd 256
#define BT (Bb*Tt)
#define MAXE 64
#define NT 8              // Tt / 128 tiles
#define NPAIR 36          // NT*(NT+1)/2
#define LN_EPS 1e-5f
#define EPS_ADJ 1e-6f

// ---------------- device scratch ----------------
__device__ float    g_xn[BT*Dd];
__device__ float    g_s0[BT*Dd];
__device__ float    g_s1[BT*Dd];
__device__ float    g_mf[BT];
__device__ int      g_top2[BT*2];
__device__ unsigned g_bits[BT*(Tt/32)];
__device__ float    g_rinv[BT];
__device__ int      g_ecols[BT*MAXE];
__device__ float    g_evals[BT*MAXE];
__device__ int      g_ecnt[BT];
__device__ float    g_cv[BT*16];   // 8 slots x 2 candidates per row
__device__ int      g_ci[BT*16];

// ---------------- row normalize + mask cast ----------------
__global__ void k_normalize(const float* __restrict__ x, const int* __restrict__ mask) {
    int row = blockIdx.x;
    int d = threadIdx.x;
    float v = x[row*Dd + d];
    __shared__ float red[8];
    float ss = v*v;
    #pragma unroll
    for (int o = 16; o; o >>= 1) ss += __shfl_xor_sync(~0u, ss, o);
    if ((threadIdx.x & 31) == 0) red[threadIdx.x >> 5] = ss;
    __syncthreads();
    if (threadIdx.x < 8) {
        float t = red[threadIdx.x];
        #pragma unroll
        for (int o = 4; o; o >>= 1) t += __shfl_xor_sync(0xff, t, o);
        if (threadIdx.x == 0) red[0] = t;
    }
    __syncthreads();
    float rn = 1.f / fmaxf(sqrtf(red[0]), 1e-12f);
    g_xn[row*Dd + d] = v * rn;
    if (d == 0) g_mf[row] = (float)mask[row];
}

// ================= symmetric sim: one 128x128 tile-pair per block =================
#define TIr 128
#define TJc 128
#define KT  16

__device__ __forceinline__ bool tgt(float v, int j, float v2, int j2) {
    return (v > v2) || (v == v2 && j < j2);
}

union SimSm {
    struct { float As[KT][TIr+4]; float Bs[KT][TJc+4]; } g;
    struct { float cv[128][32]; int ci[128][32]; } e;
};

__global__ __launch_bounds__(256, 2) void k_simtop2_sym() {
    __shared__ SimSm sm;
    __shared__ float rmask[TIr];
    __shared__ float smask[TJc];

    int b = blockIdx.y;
    int rb = b * Tt;
    // decode pair (ti <= tj)
    int rem = blockIdx.x, ti = 0;
    while (rem >= NT - ti) { rem -= NT - ti; ti++; }
    int tj = ti + rem;
    int i0 = ti * 128, j0 = tj * 128;

    int tid = threadIdx.x;
    int tx = tid & 15, ty = tid >> 4;
    int lr = tid >> 1;
    int lk = (tid & 1) * 8;

    if (tid < TIr) rmask[tid] = g_mf[rb + i0 + tid];
    if (tid < TJc) smask[tid] = g_mf[rb + j0 + tid];

    float acc[8][8];
    #pragma unroll
    for (int r = 0; r < 8; r++)
        #pragma unroll
        for (int c = 0; c < 8; c++) acc[r][c] = 0.f;

    for (int k0 = 0; k0 < Dd; k0 += KT) {
        __syncthreads();
        {
            const float4 a0 = *(const float4*)&g_xn[(rb+i0+lr)*Dd + k0 + lk];
            const float4 a1 = *(const float4*)&g_xn[(rb+i0+lr)*Dd + k0 + lk + 4];
            sm.g.As[lk+0][lr] = a0.x; sm.g.As[lk+1][lr] = a0.y;
            sm.g.As[lk+2][lr] = a0.z; sm.g.As[lk+3][lr] = a0.w;
            sm.g.As[lk+4][lr] = a1.x; sm.g.As[lk+5][lr] = a1.y;
            sm.g.As[lk+6][lr] = a1.z; sm.g.As[lk+7][lr] = a1.w;
            const float4 b0 = *(const float4*)&g_xn[(rb+j0+lr)*Dd + k0 + lk];
            const float4 b1 = *(const float4*)&g_xn[(rb+j0+lr)*Dd + k0 + lk + 4];
            sm.g.Bs[lk+0][lr] = b0.x; sm.g.Bs[lk+1][lr] = b0.y;
            sm.g.Bs[lk+2][lr] = b0.z; sm.g.Bs[lk+3][lr] = b0.w;
            sm.g.Bs[lk+4][lr] = b1.x; sm.g.Bs[lk+5][lr] = b1.y;
            sm.g.Bs[lk+6][lr] = b1.z; sm.g.Bs[lk+7][lr] = b1.w;
        }
        __syncthreads();
        #pragma unroll
        for (int k = 0; k < KT; k++) {
            float4 a0 = *(const float4*)&sm.g.As[k][ty*8 + 0];
            float4 a1 = *(const float4*)&sm.g.As[k][ty*8 + 4];
            float4 b0 = *(const float4*)&sm.g.Bs[k][tx*8 + 0];
            float4 b1 = *(const float4*)&sm.g.Bs[k][tx*8 + 4];
            float ar[8] = {a0.x,a0.y,a0.z,a0.w,a1.x,a1.y,a1.z,a1.w};
            float br[8] = {b0.x,b0.y,b0.z,b0.w,b1.x,b1.y,b1.z,b1.w};
            #pragma unroll
            for (int r = 0; r < 8; r++)
                #pragma unroll
                for (int c = 0; c < 8; c++)
                    acc[r][c] = fmaf(ar[r], br[c], acc[r][c]);
        }
    }
    __syncthreads();   // done with As/Bs; union may be reused below

    bool diag = (ti == tj);

    // ---- row-side top-2 (rows of tile ti), merged via shfl across 16 tx lanes ----
    #pragma unroll
    for (int r = 0; r < 8; r++) {
        int lrow = ty*8 + r;
        int gi = i0 + lrow;
        float mi = rmask[lrow];
        float v1 = -1e30f, v2 = -1e30f; int j1 = 0, j2 = 0;
        #pragma unroll
        for (int c = 0; c < 8; c++) {
            int gj = j0 + tx*8 + c;
            float s = acc[r][c] * mi * smask[tx*8 + c];
            if (diag && gj == gi) s = -1.0f;
            if (s > v1)      { v2=v1; j2=j1; v1=s; j1=gj; }
            else if (s > v2) { v2=s; j2=gj; }
        }
        #pragma unroll
        for (int off = 8; off; off >>= 1) {
            float ov1 = __shfl_down_sync(~0u, v1, off, 16);
            int   oj1 = __shfl_down_sync(~0u, j1, off, 16);
            float ov2 = __shfl_down_sync(~0u, v2, off, 16);
            int   oj2 = __shfl_down_sync(~0u, j2, off, 16);
            if (tgt(ov1, oj1, v1, j1)) { v2=v1; j2=j1; v1=ov1; j1=oj1; }
            else if (tgt(ov1, oj1, v2, j2)) { v2=ov1; j2=oj1; }
            if (tgt(ov2, oj2, v1, j1)) { v2=v1; j2=j1; v1=ov2; j1=oj2; }
            else if (tgt(ov2, oj2, v2, j2)) { v2=ov2; j2=oj2; }
        }
        if (tx == 0) {
            int grow = rb + i0 + lrow;
            g_cv[grow*16 + tj*2 + 0] = v1; g_ci[grow*16 + tj*2 + 0] = j1;
            g_cv[grow*16 + tj*2 + 1] = v2; g_ci[grow*16 + tj*2 + 1] = j2;
        }
    }

    // ---- column-side top-2 (rows of tile tj), only for off-diagonal pairs ----
    if (!diag) {
        #pragma unroll
        for (int c = 0; c < 8; c++) {
            int lcol = tx*8 + c;
            float mj = smask[lcol];
            float v1 = -1e30f, v2 = -1e30f; int i1 = 0, i2 = 0;
            #pragma unroll
            for (int r = 0; r < 8; r++) {
                int gi = i0 + ty*8 + r;
                float s = acc[r][c] * mj * rmask[ty*8 + r];
                if (s > v1)      { v2=v1; i2=i1; v1=s; i1=gi; }
                else if (s > v2) { v2=s; i2=gi; }
            }
            sm.e.cv[lcol][ty*2 + 0] = v1; sm.e.ci[lcol][ty*2 + 0] = i1;
            sm.e.cv[lcol][ty*2 + 1] = v2; sm.e.ci[lcol][ty*2 + 1] = i2;
        }
        __syncthreads();
        if (tid < 128) {
            float v1 = -1e30f, v2 = -1e30f; int i1 = 0, i2 = 0;
            #pragma unroll 4
            for (int e = 0; e < 32; e++) {
                float v = sm.e.cv[tid][e]; int j = sm.e.ci[tid][e];
                if (tgt(v, j, v1, i1)) { v2=v1; i2=i1; v1=v; i1=j; }
                else if (tgt(v, j, v2, i2)) { v2=v; i2=j; }
            }
            int grow = rb + j0 + tid;
            g_cv[grow*16 + ti*2 + 0] = v1; g_ci[grow*16 + ti*2 + 0] = i1;
            g_cv[grow*16 + ti*2 + 1] = v2; g_ci[grow*16 + ti*2 + 1] = i2;
        }
    }
}

// ---------------- merge 16 candidates -> top-2 per row ----------------
__global__ void k_top2merge() {
    int row = blockIdx.x*256 + threadIdx.x;
    if (row >= BT) return;
    float v1 = -1e30f, v2 = -1e30f; int j1 = 0, j2 = 0;
    #pragma unroll 4
    for (int e = 0; e < 16; e++) {
        float v = g_cv[row*16 + e]; int j = g_ci[row*16 + e];
        if (tgt(v, j, v1, j1)) { v2=v1; j2=j1; v1=v; j1=j; }
        else if (tgt(v, j, v2, j2)) { v2=v; j2=j; }
    }
    g_top2[row*2 + 0] = j1;
    g_top2[row*2 + 1] = j2;
}

// ---------------- adjacency bitmap ----------------
__global__ void k_clear() {
    int i = blockIdx.x*256 + threadIdx.x;
    if (i < BT*(Tt/32)) g_bits[i] = 0u;
}

__global__ void k_setbits() {
    int row = blockIdx.x*256 + threadIdx.x;
    if (row >= BT) return;
    int b = row / Tt, i = row % Tt;
    unsigned* wb = &g_bits[row*(Tt/32)];
    atomicOr(&wb[i >> 5], 1u << (i & 31));
    if (i > 0)      atomicOr(&wb[(i-1) >> 5], 1u << ((i-1) & 31));
    if (i < Tt-1)   atomicOr(&wb[(i+1) >> 5], 1u << ((i+1) & 31));
    float mi = g_mf[row];
    #pragma unroll
    for (int t = 0; t < 2; t++) {
        int j = g_top2[row*2 + t];
        float mj = g_mf[b*Tt + j];
        if (mi*mj != 0.f) {
            atomicOr(&wb[j >> 5], 1u << (j & 31));
            atomicOr(&g_bits[(b*Tt + j)*(Tt/32) + (i >> 5)], 1u << (i & 31));
        }
    }
}

// ---------------- edge extraction (warp per row) ----------------
__global__ __launch_bounds__(256) void k_edges() {
    int warp = (blockIdx.x*256 + threadIdx.x) >> 5;
    int lane = threadIdx.x & 31;
    if (warp >= BT) return;
    int row = warp;
    int b = row / Tt, i = row % Tt;
    float a[8];
    #pragma unroll
    for (int u = 0; u < 8; u++) a[u] = g_xn[row*Dd + lane + 32*u];
    float mi = g_mf[row];
    float rowsum = 0.f;
    int cnt = 0;
    for (int w = 0; w < Tt/32; w++) {
        unsigned bitsw = g_bits[row*(Tt/32) + w];
        while (bitsw) {
            int bit = __ffs(bitsw) - 1;
            bitsw &= bitsw - 1;
            int j = w*32 + bit;
            int jr = b*Tt + j;
            float dot = 0.f;
            #pragma unroll
            for (int u = 0; u < 8; u++) dot = fmaf(a[u], g_xn[jr*Dd + lane + 32*u], dot);
            #pragma unroll
            for (int o = 16; o; o >>= 1) dot += __shfl_xor_sync(~0u, dot, o);
            float val = dot * mi * g_mf[jr];
            if (j == i) val += 1.0f;
            rowsum += val;
            if (lane == 0 && cnt < MAXE) {
                g_ecols[row*MAXE + cnt] = j;
                g_evals[row*MAXE + cnt] = val;
            }
            cnt++;
        }
    }
    if (lane == 0) {
        g_ecnt[row] = min(cnt, MAXE);
        g_rinv[row] = rsqrtf(rowsum + EPS_ADJ);
    }
}

// ---------------- sparse adj @ h ----------------
__global__ __launch_bounds__(256) void k_spmm(const float* __restrict__ hin,
                                              float* __restrict__ hout) {
    int row = blockIdx.x;
    int d = threadIdx.x;
    int b = row / Tt;
    int cnt = g_ecnt[row];
    float ri = g_rinv[row], mi = g_mf[row];
    float acc = 0.f;
    for (int e = 0; e < cnt; e++) {
        int j = g_ecols[row*MAXE + e];
        int jr = b*Tt + j;
        float w = g_evals[row*MAXE + e] * ri * g_rinv[jr] * mi * g_mf[jr];
        acc = fmaf(w, hin[jr*Dd + d], acc);
    }
    hout[row*Dd + d] = acc;
}

// ---------------- dense h @ W^T + bias + ELU (128x128 tile) ----------------
__global__ __launch_bounds__(256, 2) void k_gemm_bias_elu(const float* __restrict__ A,
                                                          const float* __restrict__ W,
                                                          const float* __restrict__ bias,
                                                          float* __restrict__ out) {
    __shared__ float As[KT][TIr+4];
    __shared__ float Bs[KT][TJc+4];
    int r0 = blockIdx.x * TIr;
    int o0 = blockIdx.y * TJc;
    int tid = threadIdx.x;
    int tx = tid & 15, ty = tid >> 4;
    int lr = tid >> 1;
    int lk = (tid & 1) * 8;

    float acc[8][8];
    #pragma unroll
    for (int r = 0; r < 8; r++)
        #pragma unroll
        for (int c = 0; c < 8; c++) acc[r][c] = 0.f;

    for (int k0 = 0; k0 < Dd; k0 += KT) {
        __syncthreads();
        {
            const float4 a0 = *(const float4*)&A[(r0+lr)*Dd + k0 + lk];
            const float4 a1 = *(const float4*)&A[(r0+lr)*Dd + k0 + lk + 4];
            As[lk+0][lr] = a0.x; As[lk+1][lr] = a0.y;
            As[lk+2][lr] = a0.z; As[lk+3][lr] = a0.w;
            As[lk+4][lr] = a1.x; As[lk+5][lr] = a1.y;
            As[lk+6][lr] = a1.z; As[lk+7][lr] = a1.w;
            const float4 b0 = *(const float4*)&W[(o0+lr)*Dd + k0 + lk];
            const float4 b1 = *(const float4*)&W[(o0+lr)*Dd + k0 + lk + 4];
            Bs[lk+0][lr] = b0.x; Bs[lk+1][lr] = b0.y;
            Bs[lk+2][lr] = b0.z; Bs[lk+3][lr] = b0.w;
            Bs[lk+4][lr] = b1.x; Bs[lk+5][lr] = b1.y;
            Bs[lk+6][lr] = b1.z; Bs[lk+7][lr] = b1.w;
        }
        __syncthreads();
        #pragma unroll
        for (int k = 0; k < KT; k++) {
            float4 a0 = *(const float4*)&As[k][ty*8 + 0];
            float4 a1 = *(const float4*)&As[k][ty*8 + 4];
            float4 b0 = *(const float4*)&Bs[k][tx*8 + 0];
            float4 b1 = *(const float4*)&Bs[k][tx*8 + 4];
            float ar[8] = {a0.x,a0.y,a0.z,a0.w,a1.x,a1.y,a1.z,a1.w};
            float br[8] = {b0.x,b0.y,b0.z,b0.w,b1.x,b1.y,b1.z,b1.w};
            #pragma unroll
            for (int r = 0; r < 8; r++)
                #pragma unroll
                for (int c = 0; c < 8; c++)
                    acc[r][c] = fmaf(ar[r], br[c], acc[r][c]);
        }
    }
    #pragma unroll
    for (int r = 0; r < 8; r++) {
        int grow = r0 + ty*8 + r;
        #pragma unroll
        for (int c = 0; c < 8; c++) {
            int o = o0 + tx*8 + c;
            float v = acc[r][c] + bias[o];
            v = (v > 0.f) ? v : expm1f(v);
            out[grow*Dd + o] = v;
        }
    }
}

// ---------------- LayerNorm over D ----------------
__global__ void k_ln(const float* __restrict__ in, const float* __restrict__ g,
                     const float* __restrict__ be, float* __restrict__ out) {
    int row = blockIdx.x;
    int d = threadIdx.x;
    float v = in[row*Dd + d];
    __shared__ float red[8];

    float s = v;
    #pragma unroll
    for (int o = 16; o; o >>= 1) s += __shfl_xor_sync(~0u, s, o);
    if ((threadIdx.x & 31) == 0) red[threadIdx.x >> 5] = s;
    __syncthreads();
    if (threadIdx.x < 8) {
        float t = red[threadIdx.x];
        #pragma unroll
        for (int o = 4; o; o >>= 1) t += __shfl_xor_sync(0xff, t, o);
        if (threadIdx.x == 0) red[0] = t;
    }
    __syncthreads();
    float mu = red[0] * (1.f/Dd);
    __syncthreads();

    float dv = v - mu;
    float s2 = dv*dv;
    #pragma unroll
    for (int o = 16; o; o >>= 1) s2 += __shfl_xor_sync(~0u, s2, o);
    if ((threadIdx.x & 31) == 0) red[threadIdx.x >> 5] = s2;
    __syncthreads();
    if (threadIdx.x < 8) {
        float t = red[threadIdx.x];
        #pragma unroll
        for (int o = 4; o; o >>= 1) t += __shfl_xor_sync(0xff, t, o);
        if (threadIdx.x == 0) red[0] = t;
    }
    __syncthreads();
    float var = red[0] * (1.f/Dd);
    out[row*Dd + d] = dv * rsqrtf(var + LN_EPS) * g[d] + be[d];
}

// ---------------- launch ----------------
extern "C" void kernel_launch(void* const* d_in, const int* in_sizes, int n_in,
                              void* d_out, int out_size) {
    const float* x    = (const float*)d_in[0];
    const int*   mask = (const int*)  d_in[1];
    const float* W0 = (const float*)d_in[2];
    const float* b0 = (const float*)d_in[3];
    const float* g0 = (const float*)d_in[4];
    const float* be0= (const float*)d_in[5];
    const float* W1 = (const float*)d_in[6];
    const float* b1 = (const float*)d_in[7];
    const float* g1 = (const float*)d_in[8];
    const float* be1= (const float*)d_in[9];
    float* out = (float*)d_out;

    float *s0, *s1;
    cudaGetSymbolAddress((void**)&s0, g_s0);
    cudaGetSymbolAddress((void**)&s1, g_s1);

    k_normalize<<<BT, 256>>>(x, mask);
    k_clear<<<(BT*(Tt/32) + 255)/256, 256>>>();
    k_simtop2_sym<<<dim3(NPAIR, Bb), 256>>>();
    k_top2merge<<<BT/256, 256>>>();
    k_setbits<<<BT/256, 256>>>();
    k_edges<<<(BT*32)/256, 256>>>();

    // layer 1
    k_spmm<<<BT, 256>>>(x, s0);
    k_gemm_bias_elu<<<dim3(BT/TIr, Dd/TJc), 256>>>(s0, W0, b0, s1);
    k_ln<<<BT, 256>>>(s1, g0, be0, s0);
    // layer 2
    k_spmm<<<BT, 256>>>(s0, s1);
    k_gemm_bias_elu<<<dim3(BT/TIr, Dd/TJc), 256>>>(s1, W1, b1, s0);
    k_ln<<<BT, 256>>>(s0, g1, be1, out);
}

// round 5
// speedup vs baseline: 1.5565x; 1.1120x over previous
#include <cuda_runtime.h>
#include <cuda_bf16.h>
#include <math.h>
#include <stdint.h>

#define Bb 32
#define Tt 1024
#define Dd 256
#define BT (Bb*Tt)
#define MAXE 64
#define NT 8
#define LN_EPS 1e-5f
#define EPS_ADJ 1e-6f
#define CAP 48
#define MARGIN 0.02f

// ---------------- device scratch ----------------
__device__ float          g_xn[BT*Dd];
__device__ __nv_bfloat16  g_xb[BT*Dd];
__device__ __nv_bfloat16  g_simb[(size_t)BT*Tt];   // 64MB approx sim
__device__ float          g_s0[BT*Dd];
__device__ float          g_s1[BT*Dd];
__device__ float          g_mf[BT];
__device__ int            g_top2[BT*2];
__device__ unsigned       g_bits[BT*(Tt/32)];
__device__ float          g_rinv[BT];
__device__ int            g_ecols[BT*MAXE];
__device__ float          g_evals[BT*MAXE];
__device__ int            g_ecnt[BT];
__device__ float          g_v2a[BT];
__device__ int            g_cand[BT*CAP];
__device__ int            g_ccnt[BT];

__device__ __forceinline__ uint32_t smem_to_u32(const void* p) {
    uint32_t a;
    asm("{ .reg .u64 t; cvta.to.shared.u64 t, %1; cvt.u32.u64 %0, t; }" : "=r"(a) : "l"(p));
    return a;
}
__device__ __forceinline__ void ldsm4(uint32_t& r0, uint32_t& r1, uint32_t& r2, uint32_t& r3, uint32_t addr) {
    asm volatile("ldmatrix.sync.aligned.m8n8.x4.shared.b16 {%0,%1,%2,%3}, [%4];"
                 : "=r"(r0), "=r"(r1), "=r"(r2), "=r"(r3) : "r"(addr));
}
__device__ __forceinline__ void mma_bf16(float* c, uint32_t a0, uint32_t a1, uint32_t a2, uint32_t a3,
                                         uint32_t b0, uint32_t b1) {
    asm volatile("mma.sync.aligned.m16n8k16.row.col.f32.bf16.bf16.f32 "
                 "{%0,%1,%2,%3},{%4,%5,%6,%7},{%8,%9},{%0,%1,%2,%3};"
                 : "+f"(c[0]), "+f"(c[1]), "+f"(c[2]), "+f"(c[3])
                 : "r"(a0), "r"(a1), "r"(a2), "r"(a3), "r"(b0), "r"(b1));
}

// ---------------- normalize + mask + bf16 copy ----------------
__global__ void k_normalize(const float* __restrict__ x, const int* __restrict__ mask) {
    int row = blockIdx.x;
    int d = threadIdx.x;
    float v = x[row*Dd + d];
    __shared__ float red[8];
    float ss = v*v;
    #pragma unroll
    for (int o = 16; o; o >>= 1) ss += __shfl_xor_sync(~0u, ss, o);
    if ((threadIdx.x & 31) == 0) red[threadIdx.x >> 5] = ss;
    __syncthreads();
    if (threadIdx.x < 8) {
        float t = red[threadIdx.x];
        #pragma unroll
        for (int o = 4; o; o >>= 1) t += __shfl_xor_sync(0xff, t, o);
        if (threadIdx.x == 0) red[0] = t;
    }
    __syncthreads();
    float rn = 1.f / fmaxf(sqrtf(red[0]), 1e-12f);
    float xv = v * rn;
    g_xn[row*Dd + d] = xv;
    g_xb[row*Dd + d] = __float2bfloat16(xv);
    if (d == 0) g_mf[row] = (float)mask[row];
}

// ============ bf16 HMMA sim + store + approx v2 ============
#define PK 264                 // smem pitch in bf16 (conflict-free for ldmatrix)
#define SMA_BYTES (128*PK*2)   // 67584
#define SM_B_OFF  SMA_BYTES
#define SM_MASK_OFF (2*SMA_BYTES)
#define SM_TOTAL (2*SMA_BYTES + 4096)

__device__ __forceinline__ void load_tile(__nv_bfloat16* dst, const __nv_bfloat16* src, int tid) {
    #pragma unroll
    for (int it = 0; it < 16; it++) {
        int unit = tid + it*256;      // 4096 16B units
        int row = unit >> 5;
        int c8  = (unit & 31) * 8;    // bf16 col
        uint4 v = *(const uint4*)(src + row*256 + c8);
        *(uint4*)(dst + row*PK + c8) = v;
    }
}

__global__ __launch_bounds__(256, 1) void k_simtc() {
    extern __shared__ char sm[];
    __nv_bfloat16* As = (__nv_bfloat16*)sm;
    __nv_bfloat16* Bs = (__nv_bfloat16*)(sm + SM_B_OFF);
    float* smask = (float*)(sm + SM_MASK_OFF);
    uint32_t smbA = smem_to_u32(As);
    uint32_t smbB = smem_to_u32(Bs);

    int b  = blockIdx.y;
    int rb = b * Tt;
    int i0 = blockIdx.x * 128;
    int tid = threadIdx.x;
    int w = tid >> 5;
    int l = tid & 31;
    int quad = l & 3, qrow = l >> 2;

    // masks for all 1024 cols
    #pragma unroll
    for (int u = 0; u < 4; u++) smask[tid + u*256] = g_mf[rb + tid + u*256];

    // A tile resident
    load_tile(As, g_xb + (size_t)(rb + i0)*Dd, tid);

    int irow0 = i0 + w*16 + qrow;       // local row for c0,c1
    int irow1 = irow0 + 8;              // local row for c2,c3
    float mi0 = g_mf[rb + irow0];
    float mi1 = g_mf[rb + irow1];

    // ldmatrix lane address bases
    uint32_t aBase = smbA + (uint32_t)(((w*16 + (l & 15))*PK + ((l >> 4) << 3)) * 2);
    uint32_t bBase = smbB + (uint32_t)(((((l >> 4) << 3) + (l & 7))*PK + (((l >> 3) & 1) << 3)) * 2);

    float v1a = -1e30f, v2a = -1e30f, v1b = -1e30f, v2b = -1e30f;

    for (int jc = 0; jc < 8; jc++) {
        __syncthreads();
        load_tile(Bs, g_xb + (size_t)(rb + jc*128)*Dd, tid);
        __syncthreads();

        float acc[16][4];
        #pragma unroll
        for (int n = 0; n < 16; n++)
            #pragma unroll
            for (int q = 0; q < 4; q++) acc[n][q] = 0.f;

        #pragma unroll
        for (int kk = 0; kk < 16; kk++) {
            uint32_t a0, a1, a2, a3;
            ldsm4(a0, a1, a2, a3, aBase + kk*32);
            #pragma unroll
            for (int p = 0; p < 8; p++) {
                uint32_t b0, b1, b2, b3;
                ldsm4(b0, b1, b2, b3, bBase + p*(16*PK*2) + kk*32);
                mma_bf16(acc[2*p],   a0, a1, a2, a3, b0, b1);
                mma_bf16(acc[2*p+1], a0, a1, a2, a3, b2, b3);
            }
        }

        // epilogue: mask, store bf16 sim, track approx top-2
        #pragma unroll
        for (int n = 0; n < 16; n++) {
            int col = jc*128 + n*8 + quad*2;
            float s0 = acc[n][0] * mi0 * smask[col];
            float s1 = acc[n][1] * mi0 * smask[col+1];
            float s2 = acc[n][2] * mi1 * smask[col];
            float s3 = acc[n][3] * mi1 * smask[col+1];
            __nv_bfloat162 h0 = __float22bfloat162_rn(make_float2(s0, s1));
            __nv_bfloat162 h1 = __float22bfloat162_rn(make_float2(s2, s3));
            *(__nv_bfloat162*)&g_simb[(size_t)(rb + irow0)*Tt + col] = h0;
            *(__nv_bfloat162*)&g_simb[(size_t)(rb + irow1)*Tt + col] = h1;
            if (col   != irow0) { if (s0 > v1a) { v2a = v1a; v1a = s0; } else if (s0 > v2a) v2a = s0; }
            if (col+1 != irow0) { if (s1 > v1a) { v2a = v1a; v1a = s1; } else if (s1 > v2a) v2a = s1; }
            if (col   != irow1) { if (s2 > v1b) { v2b = v1b; v1b = s2; } else if (s2 > v2b) v2b = s2; }
            if (col+1 != irow1) { if (s3 > v1b) { v2b = v1b; v1b = s3; } else if (s3 > v2b) v2b = s3; }
        }
    }
    // reduce across quad (4 lanes share each row)
    #pragma unroll
    for (int off = 1; off < 4; off <<= 1) {
        float o1 = __shfl_xor_sync(~0u, v1a, off);
        float o2 = __shfl_xor_sync(~0u, v2a, off);
        if (o1 > v1a) { v2a = fmaxf(v1a, o2); v1a = o1; } else v2a = fmaxf(v2a, o1);
        o1 = __shfl_xor_sync(~0u, v1b, off);
        o2 = __shfl_xor_sync(~0u, v2b, off);
        if (o1 > v1b) { v2b = fmaxf(v1b, o2); v1b = o1; } else v2b = fmaxf(v2b, o1);
    }
    if (quad == 0) {
        g_v2a[rb + irow0] = v2a;
        g_v2a[rb + irow1] = v2b;
    }
}

// ---------------- candidate collection (thread per row, in index order) ----------------
__global__ __launch_bounds__(256) void k_cand() {
    int row = blockIdx.x*256 + threadIdx.x;
    if (row >= BT) return;
    int i = row & (Tt-1);
    float thr = g_v2a[row] - MARGIN;
    const uint4* p = (const uint4*)(g_simb + (size_t)row*Tt);
    int cnt = 0;
    for (int u = 0; u < Tt/8; u++) {
        uint4 v = p[u];
        uint32_t parts[4] = {v.x, v.y, v.z, v.w};
        #pragma unroll
        for (int h = 0; h < 4; h++) {
            float2 f = __bfloat1622float2(*(__nv_bfloat162*)&parts[h]);
            int j0 = u*8 + h*2;
            if (f.x >= thr && j0   != i && cnt < CAP) g_cand[(size_t)row*CAP + cnt++] = j0;
            if (f.y >= thr && j0+1 != i && cnt < CAP) g_cand[(size_t)row*CAP + cnt++] = j0+1;
        }
    }
    g_ccnt[row] = cnt;
}

// ---------------- exact fp32 rescore -> top-2 ----------------
__device__ __forceinline__ bool tgt(float v, int j, float v2, int j2) {
    return (v > v2) || (v == v2 && j < j2);
}

__global__ __launch_bounds__(256) void k_rescore() {
    int warp = (blockIdx.x*256 + threadIdx.x) >> 5;
    int lane = threadIdx.x & 31;
    if (warp >= BT) return;
    int row = warp;
    int b = row / Tt;
    float a[8];
    #pragma unroll
    for (int u = 0; u < 8; u++) a[u] = g_xn[row*Dd + lane + 32*u];
    float mi = g_mf[row];
    int cnt = g_ccnt[row];
    float v1 = -1e30f, v2 = -1e30f; int j1 = 0, j2 = 0;
    for (int e = 0; e < cnt; e++) {
        int j = g_cand[(size_t)row*CAP + e];
        int jr = b*Tt + j;
        float dot = 0.f;
        #pragma unroll
        for (int u = 0; u < 8; u++) dot = fmaf(a[u], g_xn[jr*Dd + lane + 32*u], dot);
        #pragma unroll
        for (int o = 16; o; o >>= 1) dot += __shfl_xor_sync(~0u, dot, o);
        float s = dot * mi * g_mf[jr];
        if (tgt(s, j, v1, j1)) { v2 = v1; j2 = j1; v1 = s; j1 = j; }
        else if (tgt(s, j, v2, j2)) { v2 = s; j2 = j; }
    }
    if (lane == 0) {
        g_top2[row*2 + 0] = j1;
        g_top2[row*2 + 1] = j2;
    }
}

// ---------------- adjacency bitmap ----------------
__global__ void k_clear() {
    int i = blockIdx.x*256 + threadIdx.x;
    if (i < BT*(Tt/32)) g_bits[i] = 0u;
}

__global__ void k_setbits() {
    int row = blockIdx.x*256 + threadIdx.x;
    if (row >= BT) return;
    int b = row / Tt, i = row % Tt;
    unsigned* wb = &g_bits[row*(Tt/32)];
    atomicOr(&wb[i >> 5], 1u << (i & 31));
    if (i > 0)      atomicOr(&wb[(i-1) >> 5], 1u << ((i-1) & 31));
    if (i < Tt-1)   atomicOr(&wb[(i+1) >> 5], 1u << ((i+1) & 31));
    float mi = g_mf[row];
    #pragma unroll
    for (int t = 0; t < 2; t++) {
        int j = g_top2[row*2 + t];
        float mj = g_mf[b*Tt + j];
        if (mi*mj != 0.f) {
            atomicOr(&wb[j >> 5], 1u << (j & 31));
            atomicOr(&g_bits[(b*Tt + j)*(Tt/32) + (i >> 5)], 1u << (i & 31));
        }
    }
}

// ---------------- edge extraction (warp per row) ----------------
__global__ __launch_bounds__(256) void k_edges() {
    int warp = (blockIdx.x*256 + threadIdx.x) >> 5;
    int lane = threadIdx.x & 31;
    if (warp >= BT) return;
    int row = warp;
    int b = row / Tt, i = row % Tt;
    float a[8];
    #pragma unroll
    for (int u = 0; u < 8; u++) a[u] = g_xn[row*Dd + lane + 32*u];
    float mi = g_mf[row];
    float rowsum = 0.f;
    int cnt = 0;
    for (int w = 0; w < Tt/32; w++) {
        unsigned bitsw = g_bits[row*(Tt/32) + w];
        while (bitsw) {
            int bit = __ffs(bitsw) - 1;
            bitsw &= bitsw - 1;
            int j = w*32 + bit;
            int jr = b*Tt + j;
            float dot = 0.f;
            #pragma unroll
            for (int u = 0; u < 8; u++) dot = fmaf(a[u], g_xn[jr*Dd + lane + 32*u], dot);
            #pragma unroll
            for (int o = 16; o; o >>= 1) dot += __shfl_xor_sync(~0u, dot, o);
            float val = dot * mi * g_mf[jr];
            if (j == i) val += 1.0f;
            rowsum += val;
            if (lane == 0 && cnt < MAXE) {
                g_ecols[row*MAXE + cnt] = j;
                g_evals[row*MAXE + cnt] = val;
            }
            cnt++;
        }
    }
    if (lane == 0) {
        g_ecnt[row] = min(cnt, MAXE);
        g_rinv[row] = rsqrtf(rowsum + EPS_ADJ);
    }
}

// ---------------- sparse adj @ h ----------------
__global__ __launch_bounds__(256) void k_spmm(const float* __restrict__ hin,
                                              float* __restrict__ hout) {
    int row = blockIdx.x;
    int d = threadIdx.x;
    int b = row / Tt;
    int cnt = g_ecnt[row];
    float ri = g_rinv[row], mi = g_mf[row];
    float acc = 0.f;
    for (int e = 0; e < cnt; e++) {
        int j = g_ecols[row*MAXE + e];
        int jr = b*Tt + j;
        float w = g_evals[row*MAXE + e] * ri * g_rinv[jr] * mi * g_mf[jr];
        acc = fmaf(w, hin[jr*Dd + d], acc);
    }
    hout[row*Dd + d] = acc;
}

// ---------------- dense h @ W^T + bias + ELU (128x128 tile) ----------------
#define TIr 128
#define TJc 128
#define KT  16
__global__ __launch_bounds__(256, 2) void k_gemm_bias_elu(const float* __restrict__ A,
                                                          const float* __restrict__ W,
                                                          const float* __restrict__ bias,
                                                          float* __restrict__ out) {
    __shared__ float As[KT][TIr+4];
    __shared__ float Bs[KT][TJc+4];
    int r0 = blockIdx.x * TIr;
    int o0 = blockIdx.y * TJc;
    int tid = threadIdx.x;
    int tx = tid & 15, ty = tid >> 4;
    int lr = tid >> 1;
    int lk = (tid & 1) * 8;

    float acc[8][8];
    #pragma unroll
    for (int r = 0; r < 8; r++)
        #pragma unroll
        for (int c = 0; c < 8; c++) acc[r][c] = 0.f;

    for (int k0 = 0; k0 < Dd; k0 += KT) {
        __syncthreads();
        {
            const float4 a0 = *(const float4*)&A[(r0+lr)*Dd + k0 + lk];
            const float4 a1 = *(const float4*)&A[(r0+lr)*Dd + k0 + lk + 4];
            As[lk+0][lr] = a0.x; As[lk+1][lr] = a0.y;
            As[lk+2][lr] = a0.z; As[lk+3][lr] = a0.w;
            As[lk+4][lr] = a1.x; As[lk+5][lr] = a1.y;
            As[lk+6][lr] = a1.z; As[lk+7][lr] = a1.w;
            const float4 b0 = *(const float4*)&W[(o0+lr)*Dd + k0 + lk];
            const float4 b1 = *(const float4*)&W[(o0+lr)*Dd + k0 + lk + 4];
            Bs[lk+0][lr] = b0.x; Bs[lk+1][lr] = b0.y;
            Bs[lk+2][lr] = b0.z; Bs[lk+3][lr] = b0.w;
            Bs[lk+4][lr] = b1.x; Bs[lk+5][lr] = b1.y;
            Bs[lk+6][lr] = b1.z; Bs[lk+7][lr] = b1.w;
        }
        __syncthreads();
        #pragma unroll
        for (int k = 0; k < KT; k++) {
            float4 a0 = *(const float4*)&As[k][ty*8 + 0];
            float4 a1 = *(const float4*)&As[k][ty*8 + 4];
            float4 b0 = *(const float4*)&Bs[k][tx*8 + 0];
            float4 b1 = *(const float4*)&Bs[k][tx*8 + 4];
            float ar[8] = {a0.x,a0.y,a0.z,a0.w,a1.x,a1.y,a1.z,a1.w};
            float br[8] = {b0.x,b0.y,b0.z,b0.w,b1.x,b1.y,b1.z,b1.w};
            #pragma unroll
            for (int r = 0; r < 8; r++)
                #pragma unroll
                for (int c = 0; c < 8; c++)
                    acc[r][c] = fmaf(ar[r], br[c], acc[r][c]);
        }
    }
    #pragma unroll
    for (int r = 0; r < 8; r++) {
        int grow = r0 + ty*8 + r;
        #pragma unroll
        for (int c = 0; c < 8; c++) {
            int o = o0 + tx*8 + c;
            float v = acc[r][c] + bias[o];
            v = (v > 0.f) ? v : expm1f(v);
            out[grow*Dd + o] = v;
        }
    }
}

// ---------------- LayerNorm over D ----------------
__global__ void k_ln(const float* __restrict__ in, const float* __restrict__ g,
                     const float* __restrict__ be, float* __restrict__ out) {
    int row = blockIdx.x;
    int d = threadIdx.x;
    float v = in[row*Dd + d];
    __shared__ float red[8];

    float s = v;
    #pragma unroll
    for (int o = 16; o; o >>= 1) s += __shfl_xor_sync(~0u, s, o);
    if ((threadIdx.x & 31) == 0) red[threadIdx.x >> 5] = s;
    __syncthreads();
    if (threadIdx.x < 8) {
        float t = red[threadIdx.x];
        #pragma unroll
        for (int o = 4; o; o >>= 1) t += __shfl_xor_sync(0xff, t, o);
        if (threadIdx.x == 0) red[0] = t;
    }
    __syncthreads();
    float mu = red[0] * (1.f/Dd);
    __syncthreads();

    float dv = v - mu;
    float s2 = dv*dv;
    #pragma unroll
    for (int o = 16; o; o >>= 1) s2 += __shfl_xor_sync(~0u, s2, o);
    if ((threadIdx.x & 31) == 0) red[threadIdx.x >> 5] = s2;
    __syncthreads();
    if (threadIdx.x < 8) {
        float t = red[threadIdx.x];
        #pragma unroll
        for (int o = 4; o; o >>= 1) t += __shfl_xor_sync(0xff, t, o);
        if (threadIdx.x == 0) red[0] = t;
    }
    __syncthreads();
    float var = red[0] * (1.f/Dd);
    out[row*Dd + d] = dv * rsqrtf(var + LN_EPS) * g[d] + be[d];
}

// ---------------- launch ----------------
extern "C" void kernel_launch(void* const* d_in, const int* in_sizes, int n_in,
                              void* d_out, int out_size) {
    const float* x    = (const float*)d_in[0];
    const int*   mask = (const int*)  d_in[1];
    const float* W0 = (const float*)d_in[2];
    const float* b0 = (const float*)d_in[3];
    const float* g0 = (const float*)d_in[4];
    const float* be0= (const float*)d_in[5];
    const float* W1 = (const float*)d_in[6];
    const float* b1 = (const float*)d_in[7];
    const float* g1 = (const float*)d_in[8];
    const float* be1= (const float*)d_in[9];
    float* out = (float*)d_out;

    float *s0, *s1;
    cudaGetSymbolAddress((void**)&s0, g_s0);
    cudaGetSymbolAddress((void**)&s1, g_s1);

    static int smem_set = 0;
    if (!smem_set) {
        cudaFuncSetAttribute(k_simtc, cudaFuncAttributeMaxDynamicSharedMemorySize, SM_TOTAL);
        smem_set = 1;
    }

    k_normalize<<<BT, 256>>>(x, mask);
    k_clear<<<(BT*(Tt/32) + 255)/256, 256>>>();
    k_simtc<<<dim3(NT, Bb), 256, SM_TOTAL>>>();
    k_cand<<<BT/256, 256>>>();
    k_rescore<<<BT/8, 256>>>();
    k_setbits<<<BT/256, 256>>>();
    k_edges<<<(BT*32)/256, 256>>>();

    // layer 1
    k_spmm<<<BT, 256>>>(x, s0);
    k_gemm_bias_elu<<<dim3(BT/TIr, Dd/TJc), 256>>>(s0, W0, b0, s1);
    k_ln<<<BT, 256>>>(s1, g0, be0, s0);
    // layer 2
    k_spmm<<<BT, 256>>>(s0, s1);
    k_gemm_bias_elu<<<dim3(BT/TIr, Dd/TJc), 256>>>(s1, W1, b1, s0);
    k_ln<<<BT, 256>>>(s0, g1, be1, out);
}

// round 6
// speedup vs baseline: 1.8665x; 1.1992x over previous
#include <cuda_runtime.h>
#include <cuda_bf16.h>
#include <math.h>
#include <stdint.h>

#define Bb 32
#define Tt 1024
#define Dd 256
#define BT (Bb*Tt)
#define MAXE 64
#define NT 8
#define LN_EPS 1e-5f
#define EPS_ADJ 1e-6f
#define CAP 48
#define MARGIN 0.02f

// ---------------- device scratch ----------------
__device__ float          g_xn[BT*Dd];
__device__ __nv_bfloat16  g_xb[BT*Dd];
__device__ __nv_bfloat16  g_simb[(size_t)BT*Tt];
__device__ float          g_s0[BT*Dd];
__device__ float          g_s1[BT*Dd];
__device__ float          g_mf[BT];
__device__ int            g_top2[BT*2];
__device__ unsigned       g_bits[BT*(Tt/32)];
__device__ float          g_rinv[BT];
__device__ int            g_ecols[BT*MAXE];
__device__ float          g_evals[BT*MAXE];
__device__ int            g_ecnt[BT];
__device__ float          g_v2a[BT];
__device__ int            g_cand[BT*CAP];
__device__ int            g_ccnt[BT];

__device__ __forceinline__ uint32_t smem_to_u32(const void* p) {
    uint32_t a;
    asm("{ .reg .u64 t; cvta.to.shared.u64 t, %1; cvt.u32.u64 %0, t; }" : "=r"(a) : "l"(p));
    return a;
}
__device__ __forceinline__ void ldsm4(uint32_t& r0, uint32_t& r1, uint32_t& r2, uint32_t& r3, uint32_t addr) {
    asm volatile("ldmatrix.sync.aligned.m8n8.x4.shared.b16 {%0,%1,%2,%3}, [%4];"
                 : "=r"(r0), "=r"(r1), "=r"(r2), "=r"(r3) : "r"(addr));
}
__device__ __forceinline__ void mma_bf16(float* c, uint32_t a0, uint32_t a1, uint32_t a2, uint32_t a3,
                                         uint32_t b0, uint32_t b1) {
    asm volatile("mma.sync.aligned.m16n8k16.row.col.f32.bf16.bf16.f32 "
                 "{%0,%1,%2,%3},{%4,%5,%6,%7},{%8,%9},{%0,%1,%2,%3};"
                 : "+f"(c[0]), "+f"(c[1]), "+f"(c[2]), "+f"(c[3])
                 : "r"(a0), "r"(a1), "r"(a2), "r"(a3), "r"(b0), "r"(b1));
}
__device__ __forceinline__ void mma_tf32(float* c, uint32_t a0, uint32_t a1, uint32_t a2, uint32_t a3,
                                         uint32_t b0, uint32_t b1) {
    asm volatile("mma.sync.aligned.m16n8k8.row.col.f32.tf32.tf32.f32 "
                 "{%0,%1,%2,%3},{%4,%5,%6,%7},{%8,%9},{%0,%1,%2,%3};"
                 : "+f"(c[0]), "+f"(c[1]), "+f"(c[2]), "+f"(c[3])
                 : "r"(a0), "r"(a1), "r"(a2), "r"(a3), "r"(b0), "r"(b1));
}
__device__ __forceinline__ uint32_t to_tf32(float x) {
    uint32_t u;
    asm("cvt.rna.tf32.f32 %0, %1;" : "=r"(u) : "f"(x));
    return u;
}

// ---------------- normalize + mask + bf16 copy ----------------
__global__ void k_normalize(const float* __restrict__ x, const int* __restrict__ mask) {
    int row = blockIdx.x;
    int d = threadIdx.x;
    float v = x[row*Dd + d];
    __shared__ float red[8];
    float ss = v*v;
    #pragma unroll
    for (int o = 16; o; o >>= 1) ss += __shfl_xor_sync(~0u, ss, o);
    if ((threadIdx.x & 31) == 0) red[threadIdx.x >> 5] = ss;
    __syncthreads();
    if (threadIdx.x < 8) {
        float t = red[threadIdx.x];
        #pragma unroll
        for (int o = 4; o; o >>= 1) t += __shfl_xor_sync(0xff, t, o);
        if (threadIdx.x == 0) red[0] = t;
    }
    __syncthreads();
    float rn = 1.f / fmaxf(sqrtf(red[0]), 1e-12f);
    float xv = v * rn;
    g_xn[row*Dd + d] = xv;
    g_xb[row*Dd + d] = __float2bfloat16(xv);
    if (d == 0) g_mf[row] = (float)mask[row];
}

// ============ bf16 HMMA sim + store + approx v2 ============
#define PK 264
#define SMA_BYTES (128*PK*2)
#define SM_B_OFF  SMA_BYTES
#define SM_MASK_OFF (2*SMA_BYTES)
#define SM_TOTAL (2*SMA_BYTES + 4096)

__device__ __forceinline__ void load_tile(__nv_bfloat16* dst, const __nv_bfloat16* src, int tid) {
    #pragma unroll
    for (int it = 0; it < 16; it++) {
        int unit = tid + it*256;
        int row = unit >> 5;
        int c8  = (unit & 31) * 8;
        uint4 v = *(const uint4*)(src + row*256 + c8);
        *(uint4*)(dst + row*PK + c8) = v;
    }
}

__global__ __launch_bounds__(256, 1) void k_simtc() {
    extern __shared__ char sm[];
    __nv_bfloat16* As = (__nv_bfloat16*)sm;
    __nv_bfloat16* Bs = (__nv_bfloat16*)(sm + SM_B_OFF);
    float* smask = (float*)(sm + SM_MASK_OFF);
    uint32_t smbA = smem_to_u32(As);
    uint32_t smbB = smem_to_u32(Bs);

    int b  = blockIdx.y;
    int rb = b * Tt;
    int i0 = blockIdx.x * 128;
    int tid = threadIdx.x;
    int w = tid >> 5;
    int l = tid & 31;
    int quad = l & 3, qrow = l >> 2;

    #pragma unroll
    for (int u = 0; u < 4; u++) smask[tid + u*256] = g_mf[rb + tid + u*256];

    load_tile(As, g_xb + (size_t)(rb + i0)*Dd, tid);

    int irow0 = i0 + w*16 + qrow;
    int irow1 = irow0 + 8;
    float mi0 = g_mf[rb + irow0];
    float mi1 = g_mf[rb + irow1];

    uint32_t aBase = smbA + (uint32_t)(((w*16 + (l & 15))*PK + ((l >> 4) << 3)) * 2);
    uint32_t bBase = smbB + (uint32_t)(((((l >> 4) << 3) + (l & 7))*PK + (((l >> 3) & 1) << 3)) * 2);

    float v1a = -1e30f, v2a = -1e30f, v1b = -1e30f, v2b = -1e30f;

    for (int jc = 0; jc < 8; jc++) {
        __syncthreads();
        load_tile(Bs, g_xb + (size_t)(rb + jc*128)*Dd, tid);
        __syncthreads();

        float acc[16][4];
        #pragma unroll
        for (int n = 0; n < 16; n++)
            #pragma unroll
            for (int q = 0; q < 4; q++) acc[n][q] = 0.f;

        #pragma unroll
        for (int kk = 0; kk < 16; kk++) {
            uint32_t a0, a1, a2, a3;
            ldsm4(a0, a1, a2, a3, aBase + kk*32);
            #pragma unroll
            for (int p = 0; p < 8; p++) {
                uint32_t b0, b1, b2, b3;
                ldsm4(b0, b1, b2, b3, bBase + p*(16*PK*2) + kk*32);
                mma_bf16(acc[2*p],   a0, a1, a2, a3, b0, b1);
                mma_bf16(acc[2*p+1], a0, a1, a2, a3, b2, b3);
            }
        }

        #pragma unroll
        for (int n = 0; n < 16; n++) {
            int col = jc*128 + n*8 + quad*2;
            float s0 = acc[n][0] * mi0 * smask[col];
            float s1 = acc[n][1] * mi0 * smask[col+1];
            float s2 = acc[n][2] * mi1 * smask[col];
            float s3 = acc[n][3] * mi1 * smask[col+1];
            __nv_bfloat162 h0 = __float22bfloat162_rn(make_float2(s0, s1));
            __nv_bfloat162 h1 = __float22bfloat162_rn(make_float2(s2, s3));
            *(__nv_bfloat162*)&g_simb[(size_t)(rb + irow0)*Tt + col] = h0;
            *(__nv_bfloat162*)&g_simb[(size_t)(rb + irow1)*Tt + col] = h1;
            if (col   != irow0) { if (s0 > v1a) { v2a = v1a; v1a = s0; } else if (s0 > v2a) v2a = s0; }
            if (col+1 != irow0) { if (s1 > v1a) { v2a = v1a; v1a = s1; } else if (s1 > v2a) v2a = s1; }
            if (col   != irow1) { if (s2 > v1b) { v2b = v1b; v1b = s2; } else if (s2 > v2b) v2b = s2; }
            if (col+1 != irow1) { if (s3 > v1b) { v2b = v1b; v1b = s3; } else if (s3 > v2b) v2b = s3; }
        }
    }
    #pragma unroll
    for (int off = 1; off < 4; off <<= 1) {
        float o1 = __shfl_xor_sync(~0u, v1a, off);
        float o2 = __shfl_xor_sync(~0u, v2a, off);
        if (o1 > v1a) { v2a = fmaxf(v1a, o2); v1a = o1; } else v2a = fmaxf(v2a, o1);
        o1 = __shfl_xor_sync(~0u, v1b, off);
        o2 = __shfl_xor_sync(~0u, v2b, off);
        if (o1 > v1b) { v2b = fmaxf(v1b, o2); v1b = o1; } else v2b = fmaxf(v2b, o1);
    }
    if (quad == 0) {
        g_v2a[rb + irow0] = v2a;
        g_v2a[rb + irow1] = v2b;
    }
}

// ---------------- candidate collection (warp per row, order preserved) ----------------
__global__ __launch_bounds__(256) void k_cand() {
    int warp = (blockIdx.x*256 + threadIdx.x) >> 5;
    int lane = threadIdx.x & 31;
    if (warp >= BT) return;
    int row = warp;
    int i = row & (Tt-1);
    float thr = g_v2a[row] - MARGIN;

    // lane owns contiguous elements [lane*32, lane*32+32)
    uint4 d[4];
    const uint4* p = (const uint4*)(g_simb + (size_t)row*Tt) + lane*4;
    #pragma unroll
    for (int t = 0; t < 4; t++) d[t] = p[t];

    // pass 1: count matches
    int cnt = 0;
    #pragma unroll
    for (int t = 0; t < 4; t++) {
        uint32_t parts[4] = {d[t].x, d[t].y, d[t].z, d[t].w};
        #pragma unroll
        for (int h = 0; h < 4; h++) {
            float2 f = __bfloat1622float2(*(__nv_bfloat162*)&parts[h]);
            int j0 = lane*32 + t*8 + h*2;
            if (f.x >= thr && j0   != i) cnt++;
            if (f.y >= thr && j0+1 != i) cnt++;
        }
    }
    // exclusive prefix sum across warp
    int incl = cnt;
    #pragma unroll
    for (int off = 1; off < 32; off <<= 1) {
        int n = __shfl_up_sync(~0u, incl, off);
        if (lane >= off) incl += n;
    }
    int base = incl - cnt;
    int total = __shfl_sync(~0u, incl, 31);

    // pass 2: write in order
    int k = 0;
    #pragma unroll
    for (int t = 0; t < 4; t++) {
        uint32_t parts[4] = {d[t].x, d[t].y, d[t].z, d[t].w};
        #pragma unroll
        for (int h = 0; h < 4; h++) {
            float2 f = __bfloat1622float2(*(__nv_bfloat162*)&parts[h]);
            int j0 = lane*32 + t*8 + h*2;
            if (f.x >= thr && j0 != i) {
                int pos = base + k;
                if (pos < CAP) g_cand[(size_t)row*CAP + pos] = j0;
                k++;
            }
            if (f.y >= thr && j0+1 != i) {
                int pos = base + k;
                if (pos < CAP) g_cand[(size_t)row*CAP + pos] = j0+1;
                k++;
            }
        }
    }
    if (lane == 31) g_ccnt[row] = min(total, CAP);
}

// ---------------- exact fp32 rescore -> top-2 ----------------
__device__ __forceinline__ bool tgt(float v, int j, float v2, int j2) {
    return (v > v2) || (v == v2 && j < j2);
}

__global__ __launch_bounds__(256) void k_rescore() {
    int warp = (blockIdx.x*256 + threadIdx.x) >> 5;
    int lane = threadIdx.x & 31;
    if (warp >= BT) return;
    int row = warp;
    int b = row / Tt;
    float a[8];
    #pragma unroll
    for (int u = 0; u < 8; u++) a[u] = g_xn[row*Dd + lane + 32*u];
    float mi = g_mf[row];
    int cnt = g_ccnt[row];
    float v1 = -1e30f, v2 = -1e30f; int j1 = 0, j2 = 0;
    for (int e = 0; e < cnt; e++) {
        int j = g_cand[(size_t)row*CAP + e];
        int jr = b*Tt + j;
        float dot = 0.f;
        #pragma unroll
        for (int u = 0; u < 8; u++) dot = fmaf(a[u], g_xn[jr*Dd + lane + 32*u], dot);
        #pragma unroll
        for (int o = 16; o; o >>= 1) dot += __shfl_xor_sync(~0u, dot, o);
        float s = dot * mi * g_mf[jr];
        if (tgt(s, j, v1, j1)) { v2 = v1; j2 = j1; v1 = s; j1 = j; }
        else if (tgt(s, j, v2, j2)) { v2 = s; j2 = j; }
    }
    if (lane == 0) {
        g_top2[row*2 + 0] = j1;
        g_top2[row*2 + 1] = j2;
    }
}

// ---------------- adjacency bitmap ----------------
__global__ void k_clear() {
    int i = blockIdx.x*256 + threadIdx.x;
    if (i < BT*(Tt/32)) g_bits[i] = 0u;
}

__global__ void k_setbits() {
    int row = blockIdx.x*256 + threadIdx.x;
    if (row >= BT) return;
    int b = row / Tt, i = row % Tt;
    unsigned* wb = &g_bits[row*(Tt/32)];
    atomicOr(&wb[i >> 5], 1u << (i & 31));
    if (i > 0)      atomicOr(&wb[(i-1) >> 5], 1u << ((i-1) & 31));
    if (i < Tt-1)   atomicOr(&wb[(i+1) >> 5], 1u << ((i+1) & 31));
    float mi = g_mf[row];
    #pragma unroll
    for (int t = 0; t < 2; t++) {
        int j = g_top2[row*2 + t];
        float mj = g_mf[b*Tt + j];
        if (mi*mj != 0.f) {
            atomicOr(&wb[j >> 5], 1u << (j & 31));
            atomicOr(&g_bits[(b*Tt + j)*(Tt/32) + (i >> 5)], 1u << (i & 31));
        }
    }
}

// ---------------- edge extraction (warp per row) ----------------
__global__ __launch_bounds__(256) void k_edges() {
    int warp = (blockIdx.x*256 + threadIdx.x) >> 5;
    int lane = threadIdx.x & 31;
    if (warp >= BT) return;
    int row = warp;
    int b = row / Tt, i = row % Tt;
    float a[8];
    #pragma unroll
    for (int u = 0; u < 8; u++) a[u] = g_xn[row*Dd + lane + 32*u];
    float mi = g_mf[row];
    float rowsum = 0.f;
    int cnt = 0;
    for (int w = 0; w < Tt/32; w++) {
        unsigned bitsw = g_bits[row*(Tt/32) + w];
        while (bitsw) {
            int bit = __ffs(bitsw) - 1;
            bitsw &= bitsw - 1;
            int j = w*32 + bit;
            int jr = b*Tt + j;
            float dot = 0.f;
            #pragma unroll
            for (int u = 0; u < 8; u++) dot = fmaf(a[u], g_xn[jr*Dd + lane + 32*u], dot);
            #pragma unroll
            for (int o = 16; o; o >>= 1) dot += __shfl_xor_sync(~0u, dot, o);
            float val = dot * mi * g_mf[jr];
            if (j == i) val += 1.0f;
            rowsum += val;
            if (lane == 0 && cnt < MAXE) {
                g_ecols[row*MAXE + cnt] = j;
                g_evals[row*MAXE + cnt] = val;
            }
            cnt++;
        }
    }
    if (lane == 0) {
        g_ecnt[row] = min(cnt, MAXE);
        g_rinv[row] = rsqrtf(rowsum + EPS_ADJ);
    }
}

// ---------------- sparse adj @ h ----------------
__global__ __launch_bounds__(256) void k_spmm(const float* __restrict__ hin,
                                              float* __restrict__ hout) {
    int row = blockIdx.x;
    int d = threadIdx.x;
    int b = row / Tt;
    int cnt = g_ecnt[row];
    float ri = g_rinv[row], mi = g_mf[row];
    float acc = 0.f;
    for (int e = 0; e < cnt; e++) {
        int j = g_ecols[row*MAXE + e];
        int jr = b*Tt + j;
        float w = g_evals[row*MAXE + e] * ri * g_rinv[jr] * mi * g_mf[jr];
        acc = fmaf(w, hin[jr*Dd + d], acc);
    }
    hout[row*Dd + d] = acc;
}

// ======== tf32 3-term HMMA: h @ W^T + bias + ELU ========
// smem pitch 36 floats (bank-conflict-free fragment loads)
#define GP 36
#define GAH 0
#define GAL (128*GP)
#define GBH (2*128*GP)
#define GBL (3*128*GP)
#define GSM_TOTAL (4*128*GP*4)   // 73728 bytes

__global__ __launch_bounds__(256, 2) void k_gemm_tf32(const float* __restrict__ A,
                                                      const float* __restrict__ W,
                                                      const float* __restrict__ bias,
                                                      float* __restrict__ out) {
    extern __shared__ uint32_t gsm[];
    int r0 = blockIdx.x * 128;
    int o0 = blockIdx.y * 128;
    int tid = threadIdx.x;
    int w = tid >> 5;
    int lane = tid & 31;
    int lr = lane >> 2;      // fragment row group 0..7
    int lc = lane & 3;       // fragment col group 0..3

    float acc[16][4];
    #pragma unroll
    for (int n = 0; n < 16; n++)
        #pragma unroll
        for (int q = 0; q < 4; q++) acc[n][q] = 0.f;

    int m0 = w * 16;

    for (int kc = 0; kc < 8; kc++) {
        __syncthreads();
        // load + split chunk: A[128][32], W[128][32]
        #pragma unroll
        for (int t = 0; t < 4; t++) {
            int unit = tid + t*256;          // 1024 float4 units
            int row = unit >> 3;
            int k4  = (unit & 7) * 4;
            float4 av = *(const float4*)&A[(size_t)(r0+row)*Dd + kc*32 + k4];
            float4 wv = *(const float4*)&W[(size_t)(o0+row)*Dd + kc*32 + k4];
            float af[4] = {av.x, av.y, av.z, av.w};
            float wf[4] = {wv.x, wv.y, wv.z, wv.w};
            #pragma unroll
            for (int q = 0; q < 4; q++) {
                uint32_t ah = to_tf32(af[q]);
                uint32_t al = to_tf32(af[q] - __uint_as_float(ah));
                uint32_t wh = to_tf32(wf[q]);
                uint32_t wl = to_tf32(wf[q] - __uint_as_float(wh));
                gsm[GAH + row*GP + k4 + q] = ah;
                gsm[GAL + row*GP + k4 + q] = al;
                gsm[GBH + row*GP + k4 + q] = wh;
                gsm[GBL + row*GP + k4 + q] = wl;
            }
        }
        __syncthreads();

        #pragma unroll
        for (int kk = 0; kk < 4; kk++) {
            int k0 = kk * 8;
            int ar = (m0 + lr) * GP + k0 + lc;
            uint32_t ah0 = gsm[GAH + ar];
            uint32_t ah1 = gsm[GAH + ar + 8*GP];
            uint32_t ah2 = gsm[GAH + ar + 4];
            uint32_t ah3 = gsm[GAH + ar + 8*GP + 4];
            uint32_t al0 = gsm[GAL + ar];
            uint32_t al1 = gsm[GAL + ar + 8*GP];
            uint32_t al2 = gsm[GAL + ar + 4];
            uint32_t al3 = gsm[GAL + ar + 8*GP + 4];
            #pragma unroll
            for (int p = 0; p < 16; p++) {
                int br = (p*8 + lr) * GP + k0 + lc;
                uint32_t bh0 = gsm[GBH + br];
                uint32_t bh1 = gsm[GBH + br + 4];
                uint32_t bl0 = gsm[GBL + br];
                uint32_t bl1 = gsm[GBL + br + 4];
                mma_tf32(acc[p], ah0, ah1, ah2, ah3, bh0, bh1);
                mma_tf32(acc[p], ah0, ah1, ah2, ah3, bl0, bl1);
                mma_tf32(acc[p], al0, al1, al2, al3, bh0, bh1);
            }
        }
    }

    // epilogue: bias + ELU
    #pragma unroll
    for (int p = 0; p < 16; p++) {
        int oc = o0 + p*8 + lc*2;
        float b0 = bias[oc], b1 = bias[oc+1];
        int gr0 = r0 + m0 + lr;
        float v0 = acc[p][0] + b0;
        float v1 = acc[p][1] + b1;
        float v2 = acc[p][2] + b0;
        float v3 = acc[p][3] + b1;
        v0 = (v0 > 0.f) ? v0 : expm1f(v0);
        v1 = (v1 > 0.f) ? v1 : expm1f(v1);
        v2 = (v2 > 0.f) ? v2 : expm1f(v2);
        v3 = (v3 > 0.f) ? v3 : expm1f(v3);
        *(float2*)&out[(size_t)gr0*Dd + oc]     = make_float2(v0, v1);
        *(float2*)&out[(size_t)(gr0+8)*Dd + oc] = make_float2(v2, v3);
    }
}

// ---------------- LayerNorm over D ----------------
__global__ void k_ln(const float* __restrict__ in, const float* __restrict__ g,
                     const float* __restrict__ be, float* __restrict__ out) {
    int row = blockIdx.x;
    int d = threadIdx.x;
    float v = in[row*Dd + d];
    __shared__ float red[8];

    float s = v;
    #pragma unroll
    for (int o = 16; o; o >>= 1) s += __shfl_xor_sync(~0u, s, o);
    if ((threadIdx.x & 31) == 0) red[threadIdx.x >> 5] = s;
    __syncthreads();
    if (threadIdx.x < 8) {
        float t = red[threadIdx.x];
        #pragma unroll
        for (int o = 4; o; o >>= 1) t += __shfl_xor_sync(0xff, t, o);
        if (threadIdx.x == 0) red[0] = t;
    }
    __syncthreads();
    float mu = red[0] * (1.f/Dd);
    __syncthreads();

    float dv = v - mu;
    float s2 = dv*dv;
    #pragma unroll
    for (int o = 16; o; o >>= 1) s2 += __shfl_xor_sync(~0u, s2, o);
    if ((threadIdx.x & 31) == 0) red[threadIdx.x >> 5] = s2;
    __syncthreads();
    if (threadIdx.x < 8) {
        float t = red[threadIdx.x];
        #pragma unroll
        for (int o = 4; o; o >>= 1) t += __shfl_xor_sync(0xff, t, o);
        if (threadIdx.x == 0) red[0] = t;
    }
    __syncthreads();
    float var = red[0] * (1.f/Dd);
    out[row*Dd + d] = dv * rsqrtf(var + LN_EPS) * g[d] + be[d];
}

// ---------------- launch ----------------
extern "C" void kernel_launch(void* const* d_in, const int* in_sizes, int n_in,
                              void* d_out, int out_size) {
    const float* x    = (const float*)d_in[0];
    const int*   mask = (const int*)  d_in[1];
    const float* W0 = (const float*)d_in[2];
    const float* b0 = (const float*)d_in[3];
    const float* g0 = (const float*)d_in[4];
    const float* be0= (const float*)d_in[5];
    const float* W1 = (const float*)d_in[6];
    const float* b1 = (const float*)d_in[7];
    const float* g1 = (const float*)d_in[8];
    const float* be1= (const float*)d_in[9];
    float* out = (float*)d_out;

    float *s0, *s1;
    cudaGetSymbolAddress((void**)&s0, g_s0);
    cudaGetSymbolAddress((void**)&s1, g_s1);

    cudaFuncSetAttribute(k_simtc, cudaFuncAttributeMaxDynamicSharedMemorySize, SM_TOTAL);
    cudaFuncSetAttribute(k_gemm_tf32, cudaFuncAttributeMaxDynamicSharedMemorySize, GSM_TOTAL);

    k_normalize<<<BT, 256>>>(x, mask);
    k_clear<<<(BT*(Tt/32) + 255)/256, 256>>>();
    k_simtc<<<dim3(NT, Bb), 256, SM_TOTAL>>>();
    k_cand<<<BT/8, 256>>>();
    k_rescore<<<BT/8, 256>>>();
    k_setbits<<<BT/256, 256>>>();
    k_edges<<<(BT*32)/256, 256>>>();

    // layer 1
    k_spmm<<<BT, 256>>>(x, s0);
    k_gemm_tf32<<<dim3(BT/128, Dd/128), 256, GSM_TOTAL>>>(s0, W0, b0, s1);
    k_ln<<<BT, 256>>>(s1, g0, be0, s0);
    // layer 2
    k_spmm<<<BT, 256>>>(s0, s1);
    k_gemm_tf32<<<dim3(BT/128, Dd/128), 256, GSM_TOTAL>>>(s1, W1, b1, s0);
    k_ln<<<BT, 256>>>(s0, g1, be1, out);
}